// round 2
// baseline (speedup 1.0000x reference)
#include <cuda_runtime.h>
#include <math.h>

// Problem constants
#define BATCH   4096
#define D1      200
#define OC      32
#define FW      9
#define W_IN    400
#define W_OUT   392
#define FC_LEN  12544     // OC * W_OUT
#define FC1_LEN 288       // OC * FW
#define EPS     1e-5f

#define G       8         // examples per block
#define NTHREADS 256
#define XS      408       // padded x stride (400 + 8 pad, covers w+9 overread)

// Scratch (static device globals; no allocation)
__device__ float g_Vs[FC_LEN];
__device__ float g_part[49];
__device__ float g_C;

// ---------------------------------------------------------------------------
// Kernel A: V[ow] = sum_f a_f * fc_w[f, ow];  Vs = V * s1_o;
// per-block partial of sum_ow V*(beta1_o - s1_o*m1_o)
// ---------------------------------------------------------------------------
__global__ void precompute_v(const float* __restrict__ fc_w,
                             const float* __restrict__ fc2_w,
                             const float* __restrict__ bn2_g,
                             const float* __restrict__ bn2_v,
                             const float* __restrict__ bn1_g,
                             const float* __restrict__ bn1_b,
                             const float* __restrict__ bn1_m,
                             const float* __restrict__ bn1_var) {
    __shared__ float a[W_IN];
    __shared__ float red[256];
    int tid = threadIdx.x;
    for (int f = tid; f < W_IN; f += 256)
        a[f] = fc2_w[f] * bn2_g[f] * rsqrtf(bn2_v[f] + EPS);
    __syncthreads();

    int ow = blockIdx.x * 256 + tid;      // 49*256 == 12544 exactly
    float v = 0.f;
    #pragma unroll 4
    for (int f = 0; f < W_IN; f++)
        v = fmaf(a[f], fc_w[(size_t)f * FC_LEN + ow], v);

    int o = ow / W_OUT;
    float s1 = bn1_g[o] * rsqrtf(bn1_var[o] + EPS);
    g_Vs[ow] = v * s1;

    red[tid] = v * (bn1_b[o] - s1 * bn1_m[o]);
    __syncthreads();
    for (int s = 128; s; s >>= 1) {
        if (tid < s) red[tid] += red[tid + s];
        __syncthreads();
    }
    if (tid == 0) g_part[blockIdx.x] = red[0];
}

// ---------------------------------------------------------------------------
// Kernel B: fold all f-dependent bias terms + kernel-A partials into g_C
// ---------------------------------------------------------------------------
__global__ void precompute_c(const float* __restrict__ fc2_w,
                             const float* __restrict__ fc2_b,
                             const float* __restrict__ fc_b,
                             const float* __restrict__ bn2_g,
                             const float* __restrict__ bn2_b,
                             const float* __restrict__ bn2_m,
                             const float* __restrict__ bn2_v) {
    __shared__ float red[512];
    int t = threadIdx.x;
    float v = 0.f;
    if (t < W_IN) {
        float s2 = bn2_g[t] * rsqrtf(bn2_v[t] + EPS);
        float af = fc2_w[t] * s2;
        v = fc2_w[t] * (bn2_b[t] - s2 * bn2_m[t]) + af * fc_b[t];
    }
    red[t] = v;
    __syncthreads();
    for (int s = 256; s; s >>= 1) {
        if (t < s) red[t] += red[t + s];
        __syncthreads();
    }
    if (t == 0) {
        float c = red[0] + fc2_b[0];
        for (int i = 0; i < 49; i++) c += g_part[i];
        g_C = c;
    }
}

// ---------------------------------------------------------------------------
// Main kernel: per block handles G=8 examples.
//  Phase A: gather e1,e2 -> x (with bn0 affine) into smem
//  Phase B: gather r into smem
//  Phase C: k[g][288] = r[g] . fc1_w^T + b  (warp-split-K, coalesced)
//  Phase D: z[g] = sum_{o,w} Vs[o,w] * sum_j x[g][w+j]*k[g][o*9+j]
//           (Vs staged in smem; rolling 9-tap register window over x)
// ---------------------------------------------------------------------------
__global__ void __launch_bounds__(NTHREADS) hyper_main(
    const int* __restrict__ e1_idx, const int* __restrict__ r_idx,
    const int* __restrict__ e2_idx,
    const float* __restrict__ E, const float* __restrict__ R,
    const float* __restrict__ bn0_g, const float* __restrict__ bn0_b,
    const float* __restrict__ bn0_m, const float* __restrict__ bn0_v,
    const float* __restrict__ fc1_w, const float* __restrict__ fc1_b,
    const float* __restrict__ bias, float* __restrict__ out) {

    extern __shared__ float sm[];
    float* sVs  = sm;                    // 12544
    float* sx   = sVs + FC_LEN;          // G*408 = 3264
    float* sr   = sx  + G * XS;          // G*200 = 1600
    float* sk   = sr  + G * D1;          // G*288 = 2304
    float* sred = sk  + G * FC1_LEN;     // G*256 = 2048

    int tid = threadIdx.x;
    int b0  = blockIdx.x * G;

    // stage Vs (coalesced, L2-resident after first wave)
    for (int i = tid; i < FC_LEN; i += NTHREADS) sVs[i] = g_Vs[i];

    // Phase A: x = bn0(concat(e1,e2))
    float s0 = bn0_g[0] * rsqrtf(bn0_v[0] + EPS);
    float c0 = bn0_b[0] - s0 * bn0_m[0];
    for (int i = tid; i < G * XS; i += NTHREADS) {
        int g = i / XS, w = i % XS;
        float val = 0.f;
        if (w < 200)      val = E[(size_t)e1_idx[b0 + g] * D1 + w];
        else if (w < 400) val = E[(size_t)e2_idx[b0 + g] * D1 + (w - 200)];
        sx[i] = (w < 400) ? fmaf(s0, val, c0) : 0.f;
    }

    // Phase B: gather r rows
    for (int i = tid; i < G * D1; i += NTHREADS) {
        int g = i / D1, d = i % D1;
        sr[i] = R[(size_t)r_idx[b0 + g] * D1 + d];
    }
    __syncthreads();

    // Phase C: hypernetwork k = r @ fc1_w^T + b. One warp per oj, lanes split d.
    int warp = tid >> 5, lane = tid & 31;
    for (int oj = warp; oj < FC1_LEN; oj += 8) {
        float wr[7];
        #pragma unroll
        for (int i = 0; i < 7; i++) {
            int d = lane + 32 * i;
            wr[i] = (d < D1) ? fc1_w[oj * D1 + d] : 0.f;
        }
        float ag[G];
        #pragma unroll
        for (int g = 0; g < G; g++) {
            const float* rg = sr + g * D1;
            float acc = 0.f;
            #pragma unroll
            for (int i = 0; i < 6; i++)
                acc = fmaf(wr[i], rg[lane + 32 * i], acc);
            if (lane < 8) acc = fmaf(wr[6], rg[lane + 192], acc);
            ag[g] = acc;
        }
        #pragma unroll
        for (int off = 16; off; off >>= 1)
            #pragma unroll
            for (int g = 0; g < G; g++)
                ag[g] += __shfl_xor_sync(0xffffffffu, ag[g], off);
        if (lane == 0) {
            float bb = fc1_b[oj];
            #pragma unroll
            for (int g = 0; g < G; g++) sk[g * FC1_LEN + oj] = ag[g] + bb;
        }
    }
    __syncthreads();

    // Phase D: contraction. Thread owns (o = tid/8, 49 consecutive w).
    int o  = tid >> 3;
    int ws = (tid & 7) * 49;
    float accg[G];
    #pragma unroll
    for (int g = 0; g < G; g++) {
        const float* xp = sx  + g * XS + ws;
        const float* kp = sk  + g * FC1_LEN + o * FW;
        const float* vp = sVs + o * W_OUT + ws;
        float k0 = kp[0], k1 = kp[1], k2 = kp[2], k3 = kp[3], k4 = kp[4],
              k5 = kp[5], k6 = kp[6], k7 = kp[7], k8 = kp[8];
        float x0 = xp[0], x1 = xp[1], x2 = xp[2], x3 = xp[3], x4 = xp[4],
              x5 = xp[5], x6 = xp[6], x7 = xp[7], x8 = xp[8];
        float a = 0.f;
        #pragma unroll 7
        for (int w = 0; w < 49; w++) {
            float c  = x0 * k0;
            float c2 = x1 * k1;
            c  = fmaf(x2, k2, c);
            c2 = fmaf(x3, k3, c2);
            c  = fmaf(x4, k4, c);
            c2 = fmaf(x5, k5, c2);
            c  = fmaf(x6, k6, c);
            c2 = fmaf(x7, k7, c2);
            c  = fmaf(x8, k8, c);
            a  = fmaf(vp[w], c + c2, a);
            x0 = x1; x1 = x2; x2 = x3; x3 = x4; x4 = x5;
            x5 = x6; x6 = x7; x7 = x8;
            x8 = xp[w + 9];           // pad in sx makes w=48 read safe
        }
        accg[g] = a;
    }
    #pragma unroll
    for (int g = 0; g < G; g++) sred[g * NTHREADS + tid] = accg[g];
    __syncthreads();

    // warp g reduces example g and writes output (deterministic)
    {
        float s = 0.f;
        const float* rp = sred + warp * NTHREADS;
        #pragma unroll
        for (int i = 0; i < 8; i++) s += rp[lane + 32 * i];
        #pragma unroll
        for (int off = 16; off; off >>= 1)
            s += __shfl_xor_sync(0xffffffffu, s, off);
        if (lane == 0)
            out[b0 + warp] = tanhf(s + g_C) + bias[0];
    }
}

// ---------------------------------------------------------------------------
#define SMEM_BYTES ((FC_LEN + G*XS + G*D1 + G*FC1_LEN + G*NTHREADS) * sizeof(float))

extern "C" void kernel_launch(void* const* d_in, const int* in_sizes, int n_in,
                              void* d_out, int out_size) {
    const int*   e1_idx = (const int*)d_in[0];
    const int*   r_idx  = (const int*)d_in[1];
    const int*   e2_idx = (const int*)d_in[2];
    const float* E      = (const float*)d_in[3];
    const float* R      = (const float*)d_in[4];
    const float* bn0_g  = (const float*)d_in[5];
    const float* bn0_b  = (const float*)d_in[6];
    const float* bn0_m  = (const float*)d_in[7];
    const float* bn0_v  = (const float*)d_in[8];
    const float* fc1_w  = (const float*)d_in[9];
    const float* fc1_b  = (const float*)d_in[10];
    const float* bn1_g  = (const float*)d_in[11];
    const float* bn1_b  = (const float*)d_in[12];
    const float* bn1_m  = (const float*)d_in[13];
    const float* bn1_v  = (const float*)d_in[14];
    const float* fc_w   = (const float*)d_in[15];
    const float* fc_b   = (const float*)d_in[16];
    const float* bn2_g  = (const float*)d_in[17];
    const float* bn2_b  = (const float*)d_in[18];
    const float* bn2_m  = (const float*)d_in[19];
    const float* bn2_v  = (const float*)d_in[20];
    const float* fc2_w  = (const float*)d_in[21];
    const float* fc2_b  = (const float*)d_in[22];
    const float* bias   = (const float*)d_in[23];
    float* out = (float*)d_out;

    cudaFuncSetAttribute(hyper_main, cudaFuncAttributeMaxDynamicSharedMemorySize,
                         (int)SMEM_BYTES);

    precompute_v<<<49, 256>>>(fc_w, fc2_w, bn2_g, bn2_v, bn1_g, bn1_b, bn1_m, bn1_v);
    precompute_c<<<1, 512>>>(fc2_w, fc2_b, fc_b, bn2_g, bn2_b, bn2_m, bn2_v);
    hyper_main<<<BATCH / G, NTHREADS, SMEM_BYTES>>>(
        e1_idx, r_idx, e2_idx, E, R,
        bn0_g, bn0_b, bn0_m, bn0_v,
        fc1_w, fc1_b, bias, out);
}

// round 4
// speedup vs baseline: 1.1636x; 1.1636x over previous
#include <cuda_runtime.h>
#include <math.h>

// Problem constants
#define BATCH   4096
#define D1      200
#define OC      32
#define FW      9
#define W_IN    400
#define W_OUT   392
#define FC_LEN  12544     // OC * W_OUT
#define FC1_LEN 288       // OC * FW
#define EPS     1e-5f

#define G       8         // examples per block
#define NTHREADS 256
#define XS      408       // padded x stride (400 + 8 pad, covers w+9 overread)

#define NPART   16        // f-dimension split for precompute_v
#define FCHUNK  25        // 400 / NPART

// Scratch (static device globals; no allocation)
__device__ __align__(16) float g_Vs[FC_LEN];
__device__ __align__(16) float g_Vpart[NPART * FC_LEN];
__device__ float g_part[49];
__device__ float g_C;

// ---------------------------------------------------------------------------
// Kernel A1: partial V. Block (bx, by) computes, for its 256 ow values,
// the sum over f in [by*25, by*25+25) of a_f * fc_w[f, ow].
// 49*16 = 784 blocks -> 200k threads -> enough MLP to saturate HBM.
// ---------------------------------------------------------------------------
__global__ void precompute_v_part(const float* __restrict__ fc_w,
                                  const float* __restrict__ fc2_w,
                                  const float* __restrict__ bn2_g,
                                  const float* __restrict__ bn2_v) {
    __shared__ float a[FCHUNK];
    int tid = threadIdx.x;
    int f0  = blockIdx.y * FCHUNK;
    if (tid < FCHUNK) {
        int f = f0 + tid;
        a[tid] = fc2_w[f] * bn2_g[f] * rsqrtf(bn2_v[f] + EPS);
    }
    __syncthreads();

    int ow = blockIdx.x * 256 + tid;      // 49*256 == 12544 exactly
    float v = 0.f;
    #pragma unroll
    for (int i = 0; i < FCHUNK; i++)
        v = fmaf(a[i], fc_w[(size_t)(f0 + i) * FC_LEN + ow], v);
    g_Vpart[blockIdx.y * FC_LEN + ow] = v;
}

// ---------------------------------------------------------------------------
// Kernel A2: reduce the NPART partials, fold bn1 scale -> g_Vs,
// and produce per-block partial of sum_ow V*(beta1_o - s1_o*m1_o).
// ---------------------------------------------------------------------------
__global__ void precompute_v_reduce(const float* __restrict__ bn1_g,
                                    const float* __restrict__ bn1_b,
                                    const float* __restrict__ bn1_m,
                                    const float* __restrict__ bn1_var) {
    __shared__ float red[256];
    int tid = threadIdx.x;
    int ow  = blockIdx.x * 256 + tid;

    float v = 0.f;
    #pragma unroll
    for (int p = 0; p < NPART; p++)
        v += g_Vpart[p * FC_LEN + ow];

    int o = ow / W_OUT;
    float s1 = bn1_g[o] * rsqrtf(bn1_var[o] + EPS);
    g_Vs[ow] = v * s1;

    red[tid] = v * (bn1_b[o] - s1 * bn1_m[o]);
    __syncthreads();
    for (int s = 128; s; s >>= 1) {
        if (tid < s) red[tid] += red[tid + s];
        __syncthreads();
    }
    if (tid == 0) g_part[blockIdx.x] = red[0];
}

// ---------------------------------------------------------------------------
// Kernel B: fold all f-dependent bias terms + kernel-A partials into g_C
// ---------------------------------------------------------------------------
__global__ void precompute_c(const float* __restrict__ fc2_w,
                             const float* __restrict__ fc2_b,
                             const float* __restrict__ fc_b,
                             const float* __restrict__ bn2_g,
                             const float* __restrict__ bn2_b,
                             const float* __restrict__ bn2_m,
                             const float* __restrict__ bn2_v) {
    __shared__ float red[512];
    int t = threadIdx.x;
    float v = 0.f;
    if (t < W_IN) {
        float s2 = bn2_g[t] * rsqrtf(bn2_v[t] + EPS);
        float af = fc2_w[t] * s2;
        v = fc2_w[t] * (bn2_b[t] - s2 * bn2_m[t]) + af * fc_b[t];
    }
    red[t] = v;
    __syncthreads();
    for (int s = 256; s; s >>= 1) {
        if (t < s) red[t] += red[t + s];
        __syncthreads();
    }
    if (t == 0) {
        float c = red[0] + fc2_b[0];
        for (int i = 0; i < 49; i++) c += g_part[i];
        g_C = c;
    }
}

// ---------------------------------------------------------------------------
// Main kernel: per block handles G=8 examples.
//  Phase A: gather e1,e2 -> x (with bn0 affine) into smem (float4)
//  Phase B: gather r into smem
//  Phase C: k[g][288] = r[g] . fc1_w^T + b  (warp-split-K, coalesced)
//  Phase D: z[g] = sum_{o,w} Vs[o,w] * sum_j x[g][w+j]*k[g][o*9+j]
//           (Vs staged in smem; rolling 9-tap register window over x)
// ---------------------------------------------------------------------------
__global__ void __launch_bounds__(NTHREADS) hyper_main(
    const int* __restrict__ e1_idx, const int* __restrict__ r_idx,
    const int* __restrict__ e2_idx,
    const float* __restrict__ E, const float* __restrict__ R,
    const float* __restrict__ bn0_g, const float* __restrict__ bn0_b,
    const float* __restrict__ bn0_m, const float* __restrict__ bn0_v,
    const float* __restrict__ fc1_w, const float* __restrict__ fc1_b,
    const float* __restrict__ bias, float* __restrict__ out) {

    extern __shared__ float sm[];
    float* sVs  = sm;                    // 12544
    float* sx   = sVs + FC_LEN;          // G*408 = 3264 (16B-aligned: 12544*4)
    float* sr   = sx  + G * XS;          // G*200 = 1600
    float* sk   = sr  + G * D1;          // G*288 = 2304
    float* sred = sk  + G * FC1_LEN;     // 8 warps * G = 64

    int tid = threadIdx.x;
    int b0  = blockIdx.x * G;

    // stage Vs with float4 (12544 = 3136 float4)
    {
        const float4* src = (const float4*)g_Vs;
        float4* dst = (float4*)sVs;
        for (int i = tid; i < FC_LEN / 4; i += NTHREADS) dst[i] = src[i];
    }

    // Phase A: x = bn0(concat(e1,e2)), float4 path. XS=408 -> 102 float4/g.
    float s0 = bn0_g[0] * rsqrtf(bn0_v[0] + EPS);
    float c0 = bn0_b[0] - s0 * bn0_m[0];
    {
        float4* sx4 = (float4*)sx;
        for (int i = tid; i < G * 102; i += NTHREADS) {
            int g = i / 102, q = i % 102;
            float4 v = make_float4(0.f, 0.f, 0.f, 0.f);
            if (q < 50) {
                const float4* e = (const float4*)(E + (size_t)e1_idx[b0 + g] * D1);
                float4 t = e[q];
                v.x = fmaf(s0, t.x, c0); v.y = fmaf(s0, t.y, c0);
                v.z = fmaf(s0, t.z, c0); v.w = fmaf(s0, t.w, c0);
            } else if (q < 100) {
                const float4* e = (const float4*)(E + (size_t)e2_idx[b0 + g] * D1);
                float4 t = e[q - 50];
                v.x = fmaf(s0, t.x, c0); v.y = fmaf(s0, t.y, c0);
                v.z = fmaf(s0, t.z, c0); v.w = fmaf(s0, t.w, c0);
            }
            sx4[g * 102 + q] = v;
        }
    }

    // Phase B: gather r rows
    for (int i = tid; i < G * D1; i += NTHREADS) {
        int g = i / D1, d = i % D1;
        sr[i] = R[(size_t)r_idx[b0 + g] * D1 + d];
    }
    __syncthreads();

    // Phase C: hypernetwork k = r @ fc1_w^T + b. One warp per oj, lanes split d.
    int warp = tid >> 5, lane = tid & 31;
    for (int oj = warp; oj < FC1_LEN; oj += 8) {
        float wr[7];
        #pragma unroll
        for (int i = 0; i < 7; i++) {
            int d = lane + 32 * i;
            wr[i] = (d < D1) ? fc1_w[oj * D1 + d] : 0.f;
        }
        float ag[G];
        #pragma unroll
        for (int g = 0; g < G; g++) {
            const float* rg = sr + g * D1;
            float acc = 0.f;
            #pragma unroll
            for (int i = 0; i < 6; i++)
                acc = fmaf(wr[i], rg[lane + 32 * i], acc);
            if (lane < 8) acc = fmaf(wr[6], rg[lane + 192], acc);
            ag[g] = acc;
        }
        #pragma unroll
        for (int off = 16; off; off >>= 1)
            #pragma unroll
            for (int g = 0; g < G; g++)
                ag[g] += __shfl_xor_sync(0xffffffffu, ag[g], off);
        if (lane == 0) {
            float bb = fc1_b[oj];
            #pragma unroll
            for (int g = 0; g < G; g++) sk[g * FC1_LEN + oj] = ag[g] + bb;
        }
    }
    __syncthreads();

    // Phase D: contraction. Thread owns (o = tid/8, 49 consecutive w).
    int o  = tid >> 3;
    int ws = (tid & 7) * 49;
    float accg[G];
    #pragma unroll
    for (int g = 0; g < G; g++) {
        const float* xp = sx  + g * XS + ws;
        const float* kp = sk  + g * FC1_LEN + o * FW;
        const float* vp = sVs + o * W_OUT + ws;
        float k0 = kp[0], k1 = kp[1], k2 = kp[2], k3 = kp[3], k4 = kp[4],
              k5 = kp[5], k6 = kp[6], k7 = kp[7], k8 = kp[8];
        float x0 = xp[0], x1 = xp[1], x2 = xp[2], x3 = xp[3], x4 = xp[4],
              x5 = xp[5], x6 = xp[6], x7 = xp[7], x8 = xp[8];
        float a = 0.f;
        #pragma unroll 7
        for (int w = 0; w < 49; w++) {
            float c  = x0 * k0;
            float c2 = x1 * k1;
            c  = fmaf(x2, k2, c);
            c2 = fmaf(x3, k3, c2);
            c  = fmaf(x4, k4, c);
            c2 = fmaf(x5, k5, c2);
            c  = fmaf(x6, k6, c);
            c2 = fmaf(x7, k7, c2);
            c  = fmaf(x8, k8, c);
            a  = fmaf(vp[w], c + c2, a);
            x0 = x1; x1 = x2; x2 = x3; x3 = x4; x4 = x5;
            x5 = x6; x6 = x7; x7 = x8;
            x8 = xp[w + 9];           // pad in sx makes w=48 read safe
        }
        accg[g] = a;
    }

    // Phase E: warp-level shuffle reduce, then 8-warp combine via 64-float smem
    #pragma unroll
    for (int g = 0; g < G; g++) {
        float s = accg[g];
        #pragma unroll
        for (int off = 16; off; off >>= 1)
            s += __shfl_xor_sync(0xffffffffu, s, off);
        if (lane == 0) sred[warp * G + g] = s;
    }
    __syncthreads();
    if (tid < G) {
        float s = 0.f;
        #pragma unroll
        for (int w = 0; w < 8; w++) s += sred[w * G + tid];
        out[b0 + tid] = tanhf(s + g_C) + bias[0];
    }
}

// ---------------------------------------------------------------------------
#define SMEM_BYTES ((FC_LEN + G*XS + G*D1 + G*FC1_LEN + 64) * sizeof(float))

extern "C" void kernel_launch(void* const* d_in, const int* in_sizes, int n_in,
                              void* d_out, int out_size) {
    const int*   e1_idx = (const int*)d_in[0];
    const int*   r_idx  = (const int*)d_in[1];
    const int*   e2_idx = (const int*)d_in[2];
    const float* E      = (const float*)d_in[3];
    const float* R      = (const float*)d_in[4];
    const float* bn0_g  = (const float*)d_in[5];
    const float* bn0_b  = (const float*)d_in[6];
    const float* bn0_m  = (const float*)d_in[7];
    const float* bn0_v  = (const float*)d_in[8];
    const float* fc1_w  = (const float*)d_in[9];
    const float* fc1_b  = (const float*)d_in[10];
    const float* bn1_g  = (const float*)d_in[11];
    const float* bn1_b  = (const float*)d_in[12];
    const float* bn1_m  = (const float*)d_in[13];
    const float* bn1_v  = (const float*)d_in[14];
    const float* fc_w   = (const float*)d_in[15];
    const float* fc_b   = (const float*)d_in[16];
    const float* bn2_g  = (const float*)d_in[17];
    const float* bn2_b  = (const float*)d_in[18];
    const float* bn2_m  = (const float*)d_in[19];
    const float* bn2_v  = (const float*)d_in[20];
    const float* fc2_w  = (const float*)d_in[21];
    const float* fc2_b  = (const float*)d_in[22];
    const float* bias   = (const float*)d_in[23];
    float* out = (float*)d_out;

    cudaFuncSetAttribute(hyper_main, cudaFuncAttributeMaxDynamicSharedMemorySize,
                         (int)SMEM_BYTES);

    precompute_v_part<<<dim3(49, NPART), 256>>>(fc_w, fc2_w, bn2_g, bn2_v);
    precompute_v_reduce<<<49, 256>>>(bn1_g, bn1_b, bn1_m, bn1_v);
    precompute_c<<<1, 512>>>(fc2_w, fc2_b, fc_b, bn2_g, bn2_b, bn2_m, bn2_v);
    hyper_main<<<BATCH / G, NTHREADS, SMEM_BYTES>>>(
        e1_idx, r_idx, e2_idx, E, R,
        bn0_g, bn0_b, bn0_m, bn0_v,
        fc1_w, fc1_b, bias, out);
}